// round 13
// baseline (speedup 1.0000x reference)
#include <cuda_runtime.h>
#include <cuda_bf16.h>
#include <cstdint>

// Problem dims (fixed)
#define MM   16384      // BS*L
#define KK   1024       // H
#define NN   1024       // NH*HD
#define LSEQ 2048
#define BSZ  8
#define NHD  16         // NH
#define HDD  64         // HD

// ---- K GEMM (1xTF32) tiling: chunk k16, 3 stages ----
#define KPITCH  20                        // f32 per row (16 used + 4 pad)
#define KTILE   (128 * KPITCH * 4)        // 10240
#define KSTAGE  (2 * KTILE)               // A, B = 20480
#define KSMEM   (3 * KSTAGE)              // 61440
#define KNCH    (KK / 16)                 // 64

// ---- V GEMM (bf16x3) tiling: chunk k16 (8 u32), 3 stages ----
#define VPITCH  12                        // u32 per row (8 used + 4 pad)
#define VTILE   (128 * VPITCH * 4)        // 6144
#define VSTAGE  (4 * VTILE)               // A1, A2, B1, B2 = 24576
#define VSMEM   (3 * VSTAGE)              // 73728
#define VNCH    (KK / 16)                 // 64

#define EPS  0.005f
#define FCAP 32768

// ---------------- scratch (static device globals; no allocs allowed) --------
__device__ float         g_V1[(size_t)MM * NN];
__device__ float         g_Ahi[(size_t)MM * KK];        // tf32(X)
__device__ float         g_WtKhi[(size_t)KK * NN];      // tf32(K1_w^T) [n][k]
__device__ uint32_t      g_Ab1[(size_t)MM * KK / 2];    // bf16 pairs of X
__device__ uint32_t      g_Ab2[(size_t)MM * KK / 2];    // residual pairs
__device__ uint32_t      g_Wb1[(size_t)KK * NN / 2];    // bf16 pairs of V1_w^T [n][k/2]
__device__ uint32_t      g_Wb2[(size_t)KK * NN / 2];
__device__ unsigned char g_valid[(size_t)MM * NHD];
__device__ int           g_fa[BSZ * NHD * LSEQ];
__device__ int           g_fb[BSZ * NHD * LSEQ];
__device__ int           g_ba[BSZ * NHD * LSEQ];
__device__ int           g_bb[BSZ * NHD * LSEQ];
__device__ int           g_nflag;
__device__ int           g_flags[FCAP];

// ---------------- PTX helpers ------------------------------------------------
__device__ __forceinline__ uint32_t s2u(const void* p) {
    uint32_t a;
    asm("{ .reg .u64 t; cvta.to.shared.u64 t, %1; cvt.u32.u64 %0, t; }"
        : "=r"(a) : "l"(p));
    return a;
}

__device__ __forceinline__ float tf32r(float x) {
    uint32_t u;
    asm("cvt.rna.tf32.f32 %0, %1;" : "=r"(u) : "f"(x));
    return __uint_as_float(u);
}

__device__ __forceinline__ uint32_t bfpack(float a, float b) {
    __nv_bfloat162 t = __floats2bfloat162_rn(a, b);
    return *reinterpret_cast<uint32_t*>(&t);
}
__device__ __forceinline__ float bflo(uint32_t u) {
    __nv_bfloat162 t = *reinterpret_cast<__nv_bfloat162*>(&u);
    return __bfloat162float(t.x);
}
__device__ __forceinline__ float bfhi(uint32_t u) {
    __nv_bfloat162 t = *reinterpret_cast<__nv_bfloat162*>(&u);
    return __bfloat162float(t.y);
}

#define CP16(dst, src) \
    asm volatile("cp.async.cg.shared.global [%0], [%1], 16;\n" :: "r"(dst), "l"(src))
#define CP_COMMIT()  asm volatile("cp.async.commit_group;")
#define CP_WAIT(n)   asm volatile("cp.async.wait_group %0;" :: "n"(n))

// ldmatrix x4 (bit-agnostic: works for bf16 pairs AND tf32 32-bit fragments)
#define LDMX4(r0, r1, r2, r3, addr) \
    asm volatile("ldmatrix.sync.aligned.m8n8.x4.shared.b16 {%0,%1,%2,%3}, [%4];" \
        : "=r"(r0), "=r"(r1), "=r"(r2), "=r"(r3) : "r"(addr))

// m16n8k8 tf32 MMA (u32 operand regs)
#define MMA_TF32U(c, a0, a1, a2, a3, b0, b1) \
    asm volatile( \
        "mma.sync.aligned.m16n8k8.row.col.f32.tf32.tf32.f32 " \
        "{%0,%1,%2,%3}, {%4,%5,%6,%7}, {%8,%9}, {%0,%1,%2,%3};" \
        : "+f"((c)[0]), "+f"((c)[1]), "+f"((c)[2]), "+f"((c)[3]) \
        : "r"(a0), "r"(a1), "r"(a2), "r"(a3), "r"(b0), "r"(b1))

// m16n8k16 bf16 MMA (operands are u32 bf16-pairs)
#define MMA_BF16(c, a0, a1, a2, a3, b0, b1) \
    asm volatile( \
        "mma.sync.aligned.m16n8k16.row.col.f32.bf16.bf16.f32 " \
        "{%0,%1,%2,%3}, {%4,%5,%6,%7}, {%8,%9}, {%0,%1,%2,%3};" \
        : "+f"((c)[0]), "+f"((c)[1]), "+f"((c)[2]), "+f"((c)[3]) \
        : "r"(a0), "r"(a1), "r"(a2), "r"(a3), "r"(b0), "r"(b1))

// ---------------- prep: splits of A (tf32 hi + bf16 pair x2) -----------------
__global__ __launch_bounds__(256)
void asplit_kernel(const float* __restrict__ X)
{
    if (blockIdx.x == 0 && threadIdx.x == 0) g_nflag = 0;
    const size_t n4 = (size_t)MM * KK / 4;
    const float4* x4 = (const float4*)X;
    float4* h4 = (float4*)g_Ahi;
    uint2* b14 = (uint2*)g_Ab1;
    uint2* b24 = (uint2*)g_Ab2;
    for (size_t i = (size_t)blockIdx.x * blockDim.x + threadIdx.x; i < n4;
         i += (size_t)gridDim.x * blockDim.x) {
        float4 v = x4[i], h;
        h.x = tf32r(v.x); h.y = tf32r(v.y);
        h.z = tf32r(v.z); h.w = tf32r(v.w);
        h4[i] = h;
        uint32_t p1 = bfpack(v.x, v.y);
        uint32_t p2 = bfpack(v.z, v.w);
        uint32_t r1 = bfpack(v.x - bflo(p1), v.y - bfhi(p1));
        uint32_t r2 = bfpack(v.z - bflo(p2), v.w - bfhi(p2));
        b14[i] = make_uint2(p1, p2);
        b24[i] = make_uint2(r1, r2);
    }
}

// ---------------- prep: weight transpose + split -----------------------------
__global__ __launch_bounds__(256)
void wsplit_kernel(const float* __restrict__ WK, const float* __restrict__ WV)
{
    __shared__ float t[32][33];
    const int z = blockIdx.z;
    const float* W = z ? WV : WK;
    const int n0 = blockIdx.x * 32, k0 = blockIdx.y * 32;
    const int tx = threadIdx.x, ty = threadIdx.y;
    #pragma unroll
    for (int j = 0; j < 32; j += 8)
        t[ty + j][tx] = W[(size_t)(k0 + ty + j) * NN + n0 + tx];
    __syncthreads();
    if (z == 0) {
        #pragma unroll
        for (int j = 0; j < 32; j += 8) {
            float v = t[tx][ty + j];                 // W[k0+tx][n0+ty+j]
            g_WtKhi[(size_t)(n0 + ty + j) * KK + k0 + tx] = tf32r(v);
        }
    } else {
        const int tid = ty * 32 + tx;
        const int nl  = tid & 31;
        const int kp2 = tid >> 5;
        #pragma unroll
        for (int jj = 0; jj < 2; jj++) {
            int kp = kp2 * 2 + jj;
            float v0 = t[2 * kp][nl];
            float v1 = t[2 * kp + 1][nl];
            uint32_t u1 = bfpack(v0, v1);
            uint32_t u2 = bfpack(v0 - bflo(u1), v1 - bfhi(u1));
            size_t o = (size_t)(n0 + nl) * (KK / 2) + (k0 >> 1) + kp;
            g_Wb1[o] = u1;
            g_Wb2[o] = u2;
        }
    }
}

// ---------------- K GEMM: 1xTF32, ldmatrix + 3-stage, fused dots epilogue ----
extern __shared__ char smem_raw[];
__global__ __launch_bounds__(256, 2)
void gemmK_kernel(const float* __restrict__ Ahi, const float* __restrict__ Bhi,
                  const float* __restrict__ bias, const float* __restrict__ RH)
{
    float* smem = (float*)smem_raw;
    __shared__ float sdots[128][4];
    const uint32_t sb = s2u(smem);
    const int tid  = threadIdx.x;
    const int wid  = tid >> 5;
    const int lane = tid & 31;
    const int wm   = wid >> 2;
    const int wn   = wid & 3;
    const int g    = lane >> 2;
    const int t    = lane & 3;
    const int grp  = lane >> 3;
    const int rr   = lane & 7;
    const int bm   = blockIdx.y;
    const int bn   = blockIdx.x;

    const float* Ag = Ahi + (size_t)bm * 128 * KK;
    const float* Bg = Bhi + (size_t)bn * 128 * KK;

    // ldmatrix per-lane base byte offsets (within a stage tile)
    const uint32_t aBase = (uint32_t)(((wm * 64 + (grp & 1) * 8 + rr) * KPITCH
                                      + (grp >> 1) * 4) * 4);
    const uint32_t bBase = (uint32_t)(((wn * 32 + (grp >> 1) * 8 + rr) * KPITCH
                                      + (grp & 1) * 4) * 4);

    auto load_chunk = [&](int kt, int st) {
        const uint32_t stage = sb + (uint32_t)st * KSTAGE;
        const int k0 = kt * 16;
        #pragma unroll
        for (int i = 0; i < 2; i++) {
            int idx = i * 256 + tid; int r = idx >> 2, c = idx & 3;
            CP16(stage + (uint32_t)(r * 80 + c * 16),
                 Ag + (size_t)r * KK + k0 + c * 4);
        }
        #pragma unroll
        for (int i = 0; i < 2; i++) {
            int idx = i * 256 + tid; int r = idx >> 2, c = idx & 3;
            CP16(stage + KTILE + (uint32_t)(r * 80 + c * 16),
                 Bg + (size_t)r * KK + k0 + c * 4);
        }
        CP_COMMIT();
    };

    float acc[4][4][4];
    #pragma unroll
    for (int mt = 0; mt < 4; mt++)
        #pragma unroll
        for (int nt = 0; nt < 4; nt++)
            #pragma unroll
            for (int i = 0; i < 4; i++) acc[mt][nt][i] = 0.0f;

    load_chunk(0, 0);
    load_chunk(1, 1);

    int s = 0;
    for (int kt = 0; kt < KNCH; kt++) {
        if (kt + 1 < KNCH) { CP_WAIT(1); } else { CP_WAIT(0); }
        __syncthreads();
        if (kt + 2 < KNCH) {
            int s2 = s + 2; if (s2 >= 3) s2 -= 3;
            load_chunk(kt + 2, s2);
        }
        const uint32_t stA = sb + (uint32_t)s * KSTAGE;
        const uint32_t stB = stA + KTILE;
        #pragma unroll
        for (int k8 = 0; k8 < 16; k8 += 8) {
            uint32_t bb[4][2];
            #pragma unroll
            for (int p = 0; p < 2; p++)
                LDMX4(bb[2 * p][0], bb[2 * p][1], bb[2 * p + 1][0], bb[2 * p + 1][1],
                      stB + bBase + (uint32_t)(p * 16 * KPITCH * 4 + k8 * 4));
            #pragma unroll
            for (int mt = 0; mt < 4; mt++) {
                uint32_t a0, a1, a2, a3;
                LDMX4(a0, a1, a2, a3,
                      stA + aBase + (uint32_t)(mt * 16 * KPITCH * 4 + k8 * 4));
                #pragma unroll
                for (int nt = 0; nt < 4; nt++)
                    MMA_TF32U(acc[mt][nt], a0, a1, a2, a3, bb[nt][0], bb[nt][1]);
            }
        }
        s++; if (s == 3) s = 0;
    }

    // ---- fused dots epilogue (unchanged) -----------------------------------
    float bv[4][2], rv[4][2];
    #pragma unroll
    for (int nt = 0; nt < 4; nt++) {
        const int lc = wn * 32 + nt * 8 + 2 * t;
        bv[nt][0] = bias[bn * 128 + lc];
        bv[nt][1] = bias[bn * 128 + lc + 1];
        rv[nt][0] = RH[bn * 128 + lc];
        rv[nt][1] = RH[bn * 128 + lc + 1];
    }
    #pragma unroll
    for (int mt = 0; mt < 4; mt++) {
        float p0 = 0.0f, p1 = 0.0f;
        #pragma unroll
        for (int nt = 0; nt < 4; nt++) {
            p0 += fmaxf(acc[mt][nt][0] + bv[nt][0], 0.0f) * rv[nt][0]
                + fmaxf(acc[mt][nt][1] + bv[nt][1], 0.0f) * rv[nt][1];
            p1 += fmaxf(acc[mt][nt][2] + bv[nt][0], 0.0f) * rv[nt][0]
                + fmaxf(acc[mt][nt][3] + bv[nt][1], 0.0f) * rv[nt][1];
        }
        p0 += __shfl_xor_sync(0xffffffffu, p0, 1);
        p0 += __shfl_xor_sync(0xffffffffu, p0, 2);
        p1 += __shfl_xor_sync(0xffffffffu, p1, 1);
        p1 += __shfl_xor_sync(0xffffffffu, p1, 2);
        if (t == 0) {
            sdots[wm * 64 + mt * 16 + g][wn]     = p0;
            sdots[wm * 64 + mt * 16 + g + 8][wn] = p1;
        }
    }
    __syncthreads();

    {
        const int row = tid >> 1;
        const int hl  = tid & 1;
        const float dot = sdots[row][2 * hl] + sdots[row][2 * hl + 1];
        const int grow = bm * 128 + row;
        const int head = bn * 2 + hl;
        g_valid[(size_t)grow * NHD + head] = (dot > 0.5f) ? 1 : 0;
        if (fabsf(dot - 0.5f) < EPS) {
            int slot = atomicAdd(&g_nflag, 1);
            if (slot < FCAP) g_flags[slot] = grow * NHD + head;
        }
    }
}

// ---------------- exact fp32 refinement of flagged dots ----------------------
__global__ __launch_bounds__(256)
void refine_kernel(const float* __restrict__ X, const float* __restrict__ W,
                   const float* __restrict__ RH)
{
    __shared__ float sred[64][5];
    __shared__ float s2[2];
    int cnt = g_nflag;
    if (cnt > FCAP) cnt = FCAP;
    const int tid = threadIdx.x;
    const int c   = tid & 63;
    const int seg = tid >> 6;

    for (int i = blockIdx.x; i < cnt; i += gridDim.x) {
        const int f    = g_flags[i];
        const int row  = f >> 4;
        const int head = f & 15;
        const float* x = X + (size_t)row * KK + seg * 256;
        const float* w = W + (size_t)(seg * 256) * NN + head * HDD + c;
        float p = 0.0f;
        #pragma unroll 8
        for (int k = 0; k < 256; k++) p += x[k] * w[(size_t)k * NN];
        sred[c][seg] = p;
        __syncthreads();
        if (tid < 64) {
            float k1 = sred[tid][0] + sred[tid][1] + sred[tid][2] + sred[tid][3];
            float v = fmaxf(k1, 0.0f) * RH[head * HDD + tid];
            #pragma unroll
            for (int o = 16; o; o >>= 1) v += __shfl_xor_sync(0xffffffffu, v, o);
            if ((tid & 31) == 0) s2[tid >> 5] = v;
        }
        __syncthreads();
        if (tid == 0)
            g_valid[(size_t)row * NHD + head] = (s2[0] + s2[1] > 0.5f) ? 1 : 0;
        __syncthreads();
    }
}

// ---------------- V GEMM: bf16x3, ldmatrix + 3-stage -------------------------
__global__ __launch_bounds__(256, 2)
void gemmV_kernel(const uint32_t* __restrict__ A1, const uint32_t* __restrict__ A2,
                  const uint32_t* __restrict__ B1, const uint32_t* __restrict__ B2,
                  const float* __restrict__ bias, float* __restrict__ C)
{
    uint32_t* smem = (uint32_t*)smem_raw;
    const uint32_t sb = s2u(smem);
    const int tid  = threadIdx.x;
    const int wid  = tid >> 5;
    const int lane = tid & 31;
    const int wm   = wid >> 2;
    const int wn   = wid & 3;
    const int g    = lane >> 2;
    const int t    = lane & 3;
    const int grp  = lane >> 3;
    const int rr   = lane & 7;
    const int bm   = blockIdx.y;
    const int bn   = blockIdx.x;

    const uint32_t* src4[4] = {
        A1 + (size_t)bm * 128 * (KK / 2), A2 + (size_t)bm * 128 * (KK / 2),
        B1 + (size_t)bn * 128 * (KK / 2), B2 + (size_t)bn * 128 * (KK / 2) };

    const uint32_t aBase = (uint32_t)(((wm * 64 + (grp & 1) * 8 + rr) * VPITCH
                                      + (grp >> 1) * 4) * 4);
    const uint32_t bBase = (uint32_t)(((wn * 32 + (grp >> 1) * 8 + rr) * VPITCH
                                      + (grp & 1) * 4) * 4);

    auto load_chunk = [&](int kt, int st) {
        const uint32_t stage = sb + (uint32_t)st * VSTAGE;
        const int kp0 = kt * 8;
        #pragma unroll
        for (int tile = 0; tile < 4; tile++) {
            int r = tid >> 1, c = tid & 1;
            CP16(stage + (uint32_t)tile * VTILE + (uint32_t)(r * 48 + c * 16),
                 src4[tile] + (size_t)r * (KK / 2) + kp0 + c * 4);
        }
        CP_COMMIT();
    };

    float acc[4][4][4];
    #pragma unroll
    for (int mt = 0; mt < 4; mt++)
        #pragma unroll
        for (int nt = 0; nt < 4; nt++)
            #pragma unroll
            for (int i = 0; i < 4; i++) acc[mt][nt][i] = 0.0f;

    load_chunk(0, 0);
    load_chunk(1, 1);

    int s = 0;
    for (int kt = 0; kt < VNCH; kt++) {
        if (kt + 1 < VNCH) { CP_WAIT(1); } else { CP_WAIT(0); }
        __syncthreads();
        if (kt + 2 < VNCH) {
            int s2 = s + 2; if (s2 >= 3) s2 -= 3;
            load_chunk(kt + 2, s2);
        }
        const uint32_t stA1 = sb + (uint32_t)s * VSTAGE;
        const uint32_t stA2 = stA1 + VTILE;
        const uint32_t stB1 = stA1 + 2 * VTILE;
        const uint32_t stB2 = stA1 + 3 * VTILE;

        uint32_t b1[4][2], b2[4][2];
        #pragma unroll
        for (int p = 0; p < 2; p++) {
            LDMX4(b1[2 * p][0], b1[2 * p][1], b1[2 * p + 1][0], b1[2 * p + 1][1],
                  stB1 + bBase + (uint32_t)(p * 16 * VPITCH * 4));
            LDMX4(b2[2 * p][0], b2[2 * p][1], b2[2 * p + 1][0], b2[2 * p + 1][1],
                  stB2 + bBase + (uint32_t)(p * 16 * VPITCH * 4));
        }
        #pragma unroll
        for (int mt = 0; mt < 4; mt++) {
            uint32_t a10, a11, a12, a13, a20, a21, a22, a23;
            LDMX4(a10, a11, a12, a13, stA1 + aBase + (uint32_t)(mt * 16 * VPITCH * 4));
            LDMX4(a20, a21, a22, a23, stA2 + aBase + (uint32_t)(mt * 16 * VPITCH * 4));
            #pragma unroll
            for (int nt = 0; nt < 4; nt++) {
                MMA_BF16(acc[mt][nt], a10, a11, a12, a13, b1[nt][0], b1[nt][1]);
                MMA_BF16(acc[mt][nt], a10, a11, a12, a13, b2[nt][0], b2[nt][1]);
                MMA_BF16(acc[mt][nt], a20, a21, a22, a23, b1[nt][0], b1[nt][1]);
            }
        }
        s++; if (s == 3) s = 0;
    }

    // epilogue: bias + relu, direct global store (unchanged)
    #pragma unroll
    for (int nt = 0; nt < 4; nt++) {
        const int col0 = bn * 128 + wn * 32 + nt * 8 + 2 * t;
        const float b0 = bias[col0], b1v = bias[col0 + 1];
        #pragma unroll
        for (int mt = 0; mt < 4; mt++) {
            const int row0 = bm * 128 + wm * 64 + mt * 16 + g;
            float v0 = fmaxf(acc[mt][nt][0] + b0, 0.0f);
            float v1 = fmaxf(acc[mt][nt][1] + b1v, 0.0f);
            float v2 = fmaxf(acc[mt][nt][2] + b0, 0.0f);
            float v3 = fmaxf(acc[mt][nt][3] + b1v, 0.0f);
            *(float2*)(C + (size_t)row0 * NN + col0)       = make_float2(v0, v1);
            *(float2*)(C + (size_t)(row0 + 8) * NN + col0) = make_float2(v2, v3);
        }
    }
}

// ---------------- parallel nearest-valid scans (exact reference semantics) ---
// block per (b,n): 256 threads, 8 elems/thread; segment top-2 summaries +
// short serial combine, then per-thread apply. Backward keeps the L-1-j quirk.
__global__ __launch_bounds__(256)
void scan_kernel()
{
    const int b = blockIdx.x >> 4;
    const int n = blockIdx.x & 15;
    const int tid = threadIdx.x;
    __shared__ unsigned char sv[LSEQ];
    __shared__ int sF1[256], sF2[256], sFc[256];
    __shared__ int sB1[256], sB2[256], sBc[256];
    __shared__ int cF1[256], cF2[256], cB1[256], cB2[256];

    for (int i = tid; i < LSEQ; i += 256)
        sv[i] = g_valid[((size_t)b * LSEQ + i) * NHD + n];
    __syncthreads();

    // segment summaries (8 elems per thread)
    {
        int v1 = 0, v2 = 0, c = 0;
        #pragma unroll
        for (int i = 0; i < 8; i++) {
            int idx = tid * 8 + i;
            if (idx >= 1 && sv[idx]) { v2 = v1; v1 = idx; c = (c < 2) ? c + 1 : 2; }
        }
        sF1[tid] = v1; sF2[tid] = v2; sFc[tid] = c;
    }
    {
        int v1 = 0, v2 = 0, c = 0;
        #pragma unroll
        for (int i = 7; i >= 0; i--) {
            int idx = tid * 8 + i;
            if (idx <= LSEQ - 2 && sv[idx]) {
                v2 = v1; v1 = (LSEQ - 1) - idx; c = (c < 2) ? c + 1 : 2;
            }
        }
        sB1[tid] = v1; sB2[tid] = v2; sBc[tid] = c;
    }
    __syncthreads();

    if (tid == 0) {            // forward exclusive carries
        int a = 0, bb2 = 0, c = 0;
        for (int s = 0; s < 256; s++) {
            cF1[s] = a; cF2[s] = bb2;
            int sc = sFc[s];
            if (sc >= 2)      { bb2 = sF2[s]; a = sF1[s]; c = 2; }
            else if (sc == 1) { bb2 = a; a = sF1[s]; c = (c < 2) ? c + 1 : 2; }
        }
    } else if (tid == 32) {    // backward exclusive carries (scan high -> low)
        int a = LSEQ - 1, bb2 = LSEQ - 1, c = 0;
        for (int s = 255; s >= 0; s--) {
            cB1[s] = a; cB2[s] = bb2;
            int sc = sBc[s];
            if (sc >= 2)      { bb2 = sB2[s]; a = sB1[s]; c = 2; }
            else if (sc == 1) { bb2 = a; a = sB1[s]; c = (c < 2) ? c + 1 : 2; }
        }
    }
    __syncthreads();

    const int base = (b * NHD + n) * LSEQ;
    {
        int a = cF1[tid], bb2 = cF2[tid];
        #pragma unroll
        for (int i = 0; i < 8; i++) {
            int idx = tid * 8 + i;
            if (idx >= 1 && sv[idx]) { bb2 = a; a = idx; }
            g_fa[base + idx] = a;
            g_fb[base + idx] = bb2;
        }
    }
    {
        int a = cB1[tid], bb2 = cB2[tid];
        #pragma unroll
        for (int i = 7; i >= 0; i--) {
            int idx = tid * 8 + i;
            if (idx <= LSEQ - 2 && sv[idx]) { bb2 = a; a = (LSEQ - 1) - idx; }
            g_ba[base + idx] = a;
            g_bb[base + idx] = bb2;
        }
    }
}

// ---------------- gather + weighted sum -------------------------------------
__global__ __launch_bounds__(256)
void gather_kernel(const float* __restrict__ bw, float* __restrict__ out)
{
    const int gw   = (int)((blockIdx.x * blockDim.x + threadIdx.x) >> 5);
    const int lane = threadIdx.x & 31;
    const int n = gw & 15;
    const int l = (gw >> 4) & (LSEQ - 1);
    const int b = gw >> 15;

    const int mbase = (b * NHD + n) * LSEQ + l;
    const int i0 = g_fa[mbase];
    const int i1 = g_fb[mbase];
    const int i2 = g_ba[mbase];
    const int i3 = g_bb[mbase];

    const float w0 = bw[n * 4 + 0];
    const float w1 = bw[n * 4 + 1];
    const float w2 = bw[n * 4 + 2];
    const float w3 = bw[n * 4 + 3];

    const size_t vbase = (size_t)b * LSEQ * NN + (size_t)n * HDD + lane;
    const float* V = g_V1;

    float o0 = w0 * V[vbase + (size_t)i0 * NN] + w1 * V[vbase + (size_t)i1 * NN]
             + w2 * V[vbase + (size_t)i2 * NN] + w3 * V[vbase + (size_t)i3 * NN];
    const size_t vb2 = vbase + 32;
    float o1 = w0 * V[vb2 + (size_t)i0 * NN] + w1 * V[vb2 + (size_t)i1 * NN]
             + w2 * V[vb2 + (size_t)i2 * NN] + w3 * V[vb2 + (size_t)i3 * NN];

    const size_t obase = ((size_t)b * LSEQ + l) * NN + (size_t)n * HDD + lane;
    out[obase]      = o0;
    out[obase + 32] = o1;
}

// ---------------- launch ------------------------------------------------------
extern "C" void kernel_launch(void* const* d_in, const int* in_sizes, int n_in,
                              void* d_out, int out_size)
{
    (void)in_sizes; (void)n_in; (void)out_size;
    const float* hid  = (const float*)d_in[0];
    const float* K1w  = (const float*)d_in[1];
    const float* K1b  = (const float*)d_in[2];
    const float* V1w  = (const float*)d_in[3];
    const float* V1b  = (const float*)d_in[4];
    const float* bw   = (const float*)d_in[5];
    const float* RH   = (const float*)d_in[6];
    float* out = (float*)d_out;

    float *pV1, *pAhi, *pWKh;
    uint32_t *pAb1, *pAb2, *pWb1, *pWb2;
    cudaGetSymbolAddress((void**)&pV1,  g_V1);
    cudaGetSymbolAddress((void**)&pAhi, g_Ahi);
    cudaGetSymbolAddress((void**)&pWKh, g_WtKhi);
    cudaGetSymbolAddress((void**)&pAb1, g_Ab1);
    cudaGetSymbolAddress((void**)&pAb2, g_Ab2);
    cudaGetSymbolAddress((void**)&pWb1, g_Wb1);
    cudaGetSymbolAddress((void**)&pWb2, g_Wb2);

    cudaFuncSetAttribute(gemmK_kernel,
                         cudaFuncAttributeMaxDynamicSharedMemorySize, KSMEM);
    cudaFuncSetAttribute(gemmV_kernel,
                         cudaFuncAttributeMaxDynamicSharedMemorySize, VSMEM);

    asplit_kernel<<<1024, 256>>>(hid);
    wsplit_kernel<<<dim3(32, 32, 2), dim3(32, 8)>>>(K1w, V1w);

    dim3 ggrid(NN / 128, MM / 128);   // (8, 128)
    gemmK_kernel<<<ggrid, 256, KSMEM>>>(pAhi, pWKh, K1b, RH);
    gemmV_kernel<<<ggrid, 256, VSMEM>>>(pAb1, pAb2, pWb1, pWb2, V1b, pV1);

    refine_kernel<<<4096, 256>>>(hid, K1w, RH);
    scan_kernel<<<BSZ * NHD, 256>>>();

    const int total_warps = BSZ * LSEQ * NHD;
    gather_kernel<<<total_warps / 8, 256>>>(bw, out);
}

// round 15
// speedup vs baseline: 1.2403x; 1.2403x over previous
#include <cuda_runtime.h>
#include <cuda_bf16.h>
#include <cstdint>

// Problem dims (fixed)
#define MM   16384      // BS*L
#define KK   1024       // H
#define NN   1024       // NH*HD
#define LSEQ 2048
#define BSZ  8
#define NHD  16         // NH
#define HDD  64         // HD

// ---- shared GEMM tiling (1xTF32, k32 chunks, 2-stage) ----
#define KKCH    32
#define KNKT    (KK / KKCH)              // 32
#define KPITCH  36                       // floats per row (32 used) - conflict free
#define KTILE_B (128 * KPITCH * 4)       // 18432
#define KSTAGE  (2 * KTILE_B)            // A, B
#define KSMEM   (2 * KSTAGE)             // 73728

#define EPS  0.005f
#define FCAP 32768

// ---------------- scratch (static device globals; no allocs allowed) --------
__device__ float         g_V1[(size_t)MM * NN];
__device__ float         g_Ahi[(size_t)MM * KK];        // tf32(X)
__device__ float         g_WtKhi[(size_t)KK * NN];      // tf32(K1_w^T) [n][k]
__device__ float         g_WtVhi[(size_t)KK * NN];      // tf32(V1_w^T) [n][k]
__device__ unsigned char g_valid[(size_t)MM * NHD];
__device__ int           g_fa[BSZ * NHD * LSEQ];
__device__ int           g_fb[BSZ * NHD * LSEQ];
__device__ int           g_ba[BSZ * NHD * LSEQ];
__device__ int           g_bb[BSZ * NHD * LSEQ];
__device__ int           g_nflag;
__device__ int           g_flags[FCAP];

// ---------------- PTX helpers ------------------------------------------------
__device__ __forceinline__ uint32_t s2u(const void* p) {
    uint32_t a;
    asm("{ .reg .u64 t; cvta.to.shared.u64 t, %1; cvt.u32.u64 %0, t; }"
        : "=r"(a) : "l"(p));
    return a;
}

__device__ __forceinline__ float tf32r(float x) {
    uint32_t u;
    asm("cvt.rna.tf32.f32 %0, %1;" : "=r"(u) : "f"(x));
    return __uint_as_float(u);
}

#define CP16(dst, src) \
    asm volatile("cp.async.cg.shared.global [%0], [%1], 16;\n" :: "r"(dst), "l"(src))
#define CP_COMMIT()  asm volatile("cp.async.commit_group;")
#define CP_WAIT(n)   asm volatile("cp.async.wait_group %0;" :: "n"(n))

// m16n8k8 tf32 MMA
#define MMA_TF32(c, a0, a1, a2, a3, b0, b1) \
    asm volatile( \
        "mma.sync.aligned.m16n8k8.row.col.f32.tf32.tf32.f32 " \
        "{%0,%1,%2,%3}, {%4,%5,%6,%7}, {%8,%9}, {%0,%1,%2,%3};" \
        : "+f"((c)[0]), "+f"((c)[1]), "+f"((c)[2]), "+f"((c)[3]) \
        : "r"(__float_as_uint(a0)), "r"(__float_as_uint(a1)), \
          "r"(__float_as_uint(a2)), "r"(__float_as_uint(a3)), \
          "r"(__float_as_uint(b0)), "r"(__float_as_uint(b1)))

// ---------------- prep: tf32 round of A (hidden states) ----------------------
__global__ __launch_bounds__(256)
void asplit_kernel(const float* __restrict__ X)
{
    if (blockIdx.x == 0 && threadIdx.x == 0) g_nflag = 0;
    const size_t n4 = (size_t)MM * KK / 4;
    const float4* x4 = (const float4*)X;
    float4* h4 = (float4*)g_Ahi;
    for (size_t i = (size_t)blockIdx.x * blockDim.x + threadIdx.x; i < n4;
         i += (size_t)gridDim.x * blockDim.x) {
        float4 v = x4[i], h;
        h.x = tf32r(v.x); h.y = tf32r(v.y);
        h.z = tf32r(v.z); h.w = tf32r(v.w);
        h4[i] = h;
    }
}

// ---------------- prep: weight transpose + tf32 round (K and V) --------------
__global__ __launch_bounds__(256)
void wsplit_kernel(const float* __restrict__ WK, const float* __restrict__ WV)
{
    __shared__ float t[32][33];
    const int z = blockIdx.z;
    const float* W = z ? WV : WK;
    float* O = z ? g_WtVhi : g_WtKhi;
    const int n0 = blockIdx.x * 32, k0 = blockIdx.y * 32;
    const int tx = threadIdx.x, ty = threadIdx.y;
    #pragma unroll
    for (int j = 0; j < 32; j += 8)
        t[ty + j][tx] = W[(size_t)(k0 + ty + j) * NN + n0 + tx];
    __syncthreads();
    #pragma unroll
    for (int j = 0; j < 32; j += 8) {
        float v = t[tx][ty + j];                 // W[k0+tx][n0+ty+j]
        O[(size_t)(n0 + ty + j) * KK + k0 + tx] = tf32r(v);
    }
}

// ================= shared 1xTF32 mainloop (r11-measured structure) ===========
extern __shared__ char smem_raw[];

// DO_DOTS=1: fused dots/valid/flag epilogue (K path). DO_DOTS=0: store C (V).
template<int DO_DOTS>
__device__ __forceinline__
void gemm_tf32_body(const float* __restrict__ Ahi, const float* __restrict__ Bhi,
                    const float* __restrict__ bias, const float* __restrict__ RH,
                    float* __restrict__ C)
{
    float* smem = (float*)smem_raw;
    __shared__ float sdots[128][4];
    const uint32_t sb = s2u(smem);
    const int tid  = threadIdx.x;
    const int wid  = tid >> 5;
    const int lane = tid & 31;
    const int wm   = wid >> 2;           // 0..1
    const int wn   = wid & 3;            // 0..3
    const int g    = lane >> 2;
    const int t    = lane & 3;
    const int bm   = blockIdx.y;
    const int bn   = blockIdx.x;

    const float* Ag = Ahi + (size_t)bm * 128 * KK;
    const float* Bg = Bhi + (size_t)bn * 128 * KK;

    auto load_chunk = [&](int kt, int s) {
        const uint32_t stage = sb + (uint32_t)s * KSTAGE;
        const int k0 = kt * KKCH;
        #pragma unroll
        for (int tile = 0; tile < 2; tile++) {
            const float* src = tile ? Bg : Ag;
            const uint32_t dst = stage + (uint32_t)tile * KTILE_B;
            #pragma unroll
            for (int i = 0; i < 4; i++) {
                int idx = i * 256 + tid;             // 0..1023
                int r = idx >> 3, c = idx & 7;
                CP16(dst + (uint32_t)(r * (KPITCH * 4) + c * 16),
                     src + (size_t)r * KK + k0 + c * 4);
            }
        }
        CP_COMMIT();
    };

    float acc[4][4][4];
    #pragma unroll
    for (int mt = 0; mt < 4; mt++)
        #pragma unroll
        for (int nt = 0; nt < 4; nt++)
            #pragma unroll
            for (int i = 0; i < 4; i++) acc[mt][nt][i] = 0.0f;

    load_chunk(0, 0);

    for (int kt = 0; kt < KNKT; kt++) {
        const int s = kt & 1;
        if (kt + 1 < KNKT) { load_chunk(kt + 1, s ^ 1); CP_WAIT(1); }
        else               { CP_WAIT(0); }
        __syncthreads();

        const float* Ah = smem + (size_t)s * (KSTAGE / 4);
        const float* Bh = Ah + KTILE_B / 4;

        #pragma unroll
        for (int k8 = 0; k8 < KKCH; k8 += 8) {
            float bf[4][2];
            #pragma unroll
            for (int nt = 0; nt < 4; nt++) {
                const int br = (wn * 32 + nt * 8 + g) * KPITCH + k8 + t;
                bf[nt][0] = Bh[br];
                bf[nt][1] = Bh[br + 4];
            }
            #pragma unroll
            for (int mt = 0; mt < 4; mt++) {
                const int ar  = (wm * 64 + mt * 16 + g) * KPITCH + k8 + t;
                const int ar8 = ar + 8 * KPITCH;
                float a0 = Ah[ar],     a1 = Ah[ar8];
                float a2 = Ah[ar + 4], a3 = Ah[ar8 + 4];
                #pragma unroll
                for (int nt = 0; nt < 4; nt++)
                    MMA_TF32(acc[mt][nt], a0, a1, a2, a3, bf[nt][0], bf[nt][1]);
            }
        }
        __syncthreads();
    }

    if (DO_DOTS) {
        // ---- fused dots epilogue (K path) ----------------------------------
        float bv[4][2], rv[4][2];
        #pragma unroll
        for (int nt = 0; nt < 4; nt++) {
            const int lc = wn * 32 + nt * 8 + 2 * t;
            bv[nt][0] = bias[bn * 128 + lc];
            bv[nt][1] = bias[bn * 128 + lc + 1];
            rv[nt][0] = RH[bn * 128 + lc];
            rv[nt][1] = RH[bn * 128 + lc + 1];
        }
        #pragma unroll
        for (int mt = 0; mt < 4; mt++) {
            float p0 = 0.0f, p1 = 0.0f;
            #pragma unroll
            for (int nt = 0; nt < 4; nt++) {
                p0 += fmaxf(acc[mt][nt][0] + bv[nt][0], 0.0f) * rv[nt][0]
                    + fmaxf(acc[mt][nt][1] + bv[nt][1], 0.0f) * rv[nt][1];
                p1 += fmaxf(acc[mt][nt][2] + bv[nt][0], 0.0f) * rv[nt][0]
                    + fmaxf(acc[mt][nt][3] + bv[nt][1], 0.0f) * rv[nt][1];
            }
            p0 += __shfl_xor_sync(0xffffffffu, p0, 1);
            p0 += __shfl_xor_sync(0xffffffffu, p0, 2);
            p1 += __shfl_xor_sync(0xffffffffu, p1, 1);
            p1 += __shfl_xor_sync(0xffffffffu, p1, 2);
            if (t == 0) {
                sdots[wm * 64 + mt * 16 + g][wn]     = p0;
                sdots[wm * 64 + mt * 16 + g + 8][wn] = p1;
            }
        }
        __syncthreads();

        const int row = tid >> 1;
        const int hl  = tid & 1;
        const float dot = sdots[row][2 * hl] + sdots[row][2 * hl + 1];
        const int grow = bm * 128 + row;
        const int head = bn * 2 + hl;
        g_valid[(size_t)grow * NHD + head] = (dot > 0.5f) ? 1 : 0;
        if (fabsf(dot - 0.5f) < EPS) {
            int slot = atomicAdd(&g_nflag, 1);
            if (slot < FCAP) g_flags[slot] = grow * NHD + head;
        }
    } else {
        // ---- bias + relu store epilogue (V path) ---------------------------
        #pragma unroll
        for (int nt = 0; nt < 4; nt++) {
            const int col0 = bn * 128 + wn * 32 + nt * 8 + 2 * t;
            const float b0 = bias[col0], b1v = bias[col0 + 1];
            #pragma unroll
            for (int mt = 0; mt < 4; mt++) {
                const int row0 = bm * 128 + wm * 64 + mt * 16 + g;
                float v0 = fmaxf(acc[mt][nt][0] + b0, 0.0f);
                float v1 = fmaxf(acc[mt][nt][1] + b1v, 0.0f);
                float v2 = fmaxf(acc[mt][nt][2] + b0, 0.0f);
                float v3 = fmaxf(acc[mt][nt][3] + b1v, 0.0f);
                *(float2*)(C + (size_t)row0 * NN + col0)       = make_float2(v0, v1);
                *(float2*)(C + (size_t)(row0 + 8) * NN + col0) = make_float2(v2, v3);
            }
        }
    }
}

__global__ __launch_bounds__(256, 2)
void gemmK_kernel(const float* __restrict__ Ahi, const float* __restrict__ Bhi,
                  const float* __restrict__ bias, const float* __restrict__ RH)
{
    gemm_tf32_body<1>(Ahi, Bhi, bias, RH, nullptr);
}

__global__ __launch_bounds__(256, 2)
void gemmV_kernel(const float* __restrict__ Ahi, const float* __restrict__ Bhi,
                  const float* __restrict__ bias, float* __restrict__ C)
{
    gemm_tf32_body<0>(Ahi, Bhi, bias, nullptr, C);
}

// ---------------- exact fp32 refinement of flagged dots ----------------------
__global__ __launch_bounds__(256)
void refine_kernel(const float* __restrict__ X, const float* __restrict__ W,
                   const float* __restrict__ RH)
{
    __shared__ float sred[64][5];
    __shared__ float s2[2];
    int cnt = g_nflag;
    if (cnt > FCAP) cnt = FCAP;
    const int tid = threadIdx.x;
    const int c   = tid & 63;
    const int seg = tid >> 6;

    for (int i = blockIdx.x; i < cnt; i += gridDim.x) {
        const int f    = g_flags[i];
        const int row  = f >> 4;
        const int head = f & 15;
        const float* x = X + (size_t)row * KK + seg * 256;
        const float* w = W + (size_t)(seg * 256) * NN + head * HDD + c;
        float p = 0.0f;
        #pragma unroll 8
        for (int k = 0; k < 256; k++) p += x[k] * w[(size_t)k * NN];
        sred[c][seg] = p;
        __syncthreads();
        if (tid < 64) {
            float k1 = sred[tid][0] + sred[tid][1] + sred[tid][2] + sred[tid][3];
            float v = fmaxf(k1, 0.0f) * RH[head * HDD + tid];
            #pragma unroll
            for (int o = 16; o; o >>= 1) v += __shfl_xor_sync(0xffffffffu, v, o);
            if ((tid & 31) == 0) s2[tid >> 5] = v;
        }
        __syncthreads();
        if (tid == 0)
            g_valid[(size_t)row * NHD + head] = (s2[0] + s2[1] > 0.5f) ? 1 : 0;
        __syncthreads();
    }
}

// ---------------- parallel nearest-valid scans (exact reference semantics) ---
__global__ __launch_bounds__(256)
void scan_kernel()
{
    const int b = blockIdx.x >> 4;
    const int n = blockIdx.x & 15;
    const int tid = threadIdx.x;
    __shared__ unsigned char sv[LSEQ];
    __shared__ int sF1[256], sF2[256], sFc[256];
    __shared__ int sB1[256], sB2[256], sBc[256];
    __shared__ int cF1[256], cF2[256], cB1[256], cB2[256];

    for (int i = tid; i < LSEQ; i += 256)
        sv[i] = g_valid[((size_t)b * LSEQ + i) * NHD + n];
    __syncthreads();

    {
        int v1 = 0, v2 = 0, c = 0;
        #pragma unroll
        for (int i = 0; i < 8; i++) {
            int idx = tid * 8 + i;
            if (idx >= 1 && sv[idx]) { v2 = v1; v1 = idx; c = (c < 2) ? c + 1 : 2; }
        }
        sF1[tid] = v1; sF2[tid] = v2; sFc[tid] = c;
    }
    {
        int v1 = 0, v2 = 0, c = 0;
        #pragma unroll
        for (int i = 7; i >= 0; i--) {
            int idx = tid * 8 + i;
            if (idx <= LSEQ - 2 && sv[idx]) {
                v2 = v1; v1 = (LSEQ - 1) - idx; c = (c < 2) ? c + 1 : 2;
            }
        }
        sB1[tid] = v1; sB2[tid] = v2; sBc[tid] = c;
    }
    __syncthreads();

    if (tid == 0) {            // forward exclusive carries
        int a = 0, bb2 = 0, c = 0;
        for (int s = 0; s < 256; s++) {
            cF1[s] = a; cF2[s] = bb2;
            int sc = sFc[s];
            if (sc >= 2)      { bb2 = sF2[s]; a = sF1[s]; c = 2; }
            else if (sc == 1) { bb2 = a; a = sF1[s]; c = (c < 2) ? c + 1 : 2; }
        }
    } else if (tid == 32) {    // backward exclusive carries
        int a = LSEQ - 1, bb2 = LSEQ - 1, c = 0;
        for (int s = 255; s >= 0; s--) {
            cB1[s] = a; cB2[s] = bb2;
            int sc = sBc[s];
            if (sc >= 2)      { bb2 = sB2[s]; a = sB1[s]; c = 2; }
            else if (sc == 1) { bb2 = a; a = sB1[s]; c = (c < 2) ? c + 1 : 2; }
        }
    }
    __syncthreads();

    const int base = (b * NHD + n) * LSEQ;
    {
        int a = cF1[tid], bb2 = cF2[tid];
        #pragma unroll
        for (int i = 0; i < 8; i++) {
            int idx = tid * 8 + i;
            if (idx >= 1 && sv[idx]) { bb2 = a; a = idx; }
            g_fa[base + idx] = a;
            g_fb[base + idx] = bb2;
        }
    }
    {
        int a = cB1[tid], bb2 = cB2[tid];
        #pragma unroll
        for (int i = 7; i >= 0; i--) {
            int idx = tid * 8 + i;
            if (idx <= LSEQ - 2 && sv[idx]) { bb2 = a; a = (LSEQ - 1) - idx; }
            g_ba[base + idx] = a;
            g_bb[base + idx] = bb2;
        }
    }
}

// ---------------- gather + weighted sum -------------------------------------
__global__ __launch_bounds__(256)
void gather_kernel(const float* __restrict__ bw, float* __restrict__ out)
{
    const int gw   = (int)((blockIdx.x * blockDim.x + threadIdx.x) >> 5);
    const int lane = threadIdx.x & 31;
    const int n = gw & 15;
    const int l = (gw >> 4) & (LSEQ - 1);
    const int b = gw >> 15;

    const int mbase = (b * NHD + n) * LSEQ + l;
    const int i0 = g_fa[mbase];
    const int i1 = g_fb[mbase];
    const int i2 = g_ba[mbase];
    const int i3 = g_bb[mbase];

    const float w0 = bw[n * 4 + 0];
    const float w1 = bw[n * 4 + 1];
    const float w2 = bw[n * 4 + 2];
    const float w3 = bw[n * 4 + 3];

    const size_t vbase = (size_t)b * LSEQ * NN + (size_t)n * HDD + lane;
    const float* V = g_V1;

    float o0 = w0 * V[vbase + (size_t)i0 * NN] + w1 * V[vbase + (size_t)i1 * NN]
             + w2 * V[vbase + (size_t)i2 * NN] + w3 * V[vbase + (size_t)i3 * NN];
    const size_t vb2 = vbase + 32;
    float o1 = w0 * V[vb2 + (size_t)i0 * NN] + w1 * V[vb2 + (size_t)i1 * NN]
             + w2 * V[vb2 + (size_t)i2 * NN] + w3 * V[vb2 + (size_t)i3 * NN];

    const size_t obase = ((size_t)b * LSEQ + l) * NN + (size_t)n * HDD + lane;
    out[obase]      = o0;
    out[obase + 32] = o1;
}

// ---------------- launch ------------------------------------------------------
extern "C" void kernel_launch(void* const* d_in, const int* in_sizes, int n_in,
                              void* d_out, int out_size)
{
    (void)in_sizes; (void)n_in; (void)out_size;
    const float* hid  = (const float*)d_in[0];
    const float* K1w  = (const float*)d_in[1];
    const float* K1b  = (const float*)d_in[2];
    const float* V1w  = (const float*)d_in[3];
    const float* V1b  = (const float*)d_in[4];
    const float* bw   = (const float*)d_in[5];
    const float* RH   = (const float*)d_in[6];
    float* out = (float*)d_out;

    float *pV1, *pAhi, *pWKh, *pWVh;
    cudaGetSymbolAddress((void**)&pV1,  g_V1);
    cudaGetSymbolAddress((void**)&pAhi, g_Ahi);
    cudaGetSymbolAddress((void**)&pWKh, g_WtKhi);
    cudaGetSymbolAddress((void**)&pWVh, g_WtVhi);

    cudaFuncSetAttribute(gemmK_kernel,
                         cudaFuncAttributeMaxDynamicSharedMemorySize, KSMEM);
    cudaFuncSetAttribute(gemmV_kernel,
                         cudaFuncAttributeMaxDynamicSharedMemorySize, KSMEM);

    asplit_kernel<<<1024, 256>>>(hid);
    wsplit_kernel<<<dim3(32, 32, 2), dim3(32, 8)>>>(K1w, V1w);

    dim3 ggrid(NN / 128, MM / 128);   // (8, 128)
    gemmK_kernel<<<ggrid, 256, KSMEM>>>(pAhi, pWKh, K1b, RH);
    gemmV_kernel<<<ggrid, 256, KSMEM>>>(pAhi, pWVh, V1b, pV1);

    refine_kernel<<<4096, 256>>>(hid, K1w, RH);
    scan_kernel<<<BSZ * NHD, 256>>>();

    const int total_warps = BSZ * LSEQ * NHD;
    gather_kernel<<<total_warps / 8, 256>>>(bw, out);
}